// round 12
// baseline (speedup 1.0000x reference)
#include <cuda_runtime.h>
#include <cuda_bf16.h>

// ImageAverage: x [N, 64] f32, image_id [N] i32 SORTED ascending in [0, n_images).
// Output (f32 concat): averaged [n_images, 64], image_id as float [N], counts [n_images].
//
// Kernel 1 (grid = 148*8 = 1184, balanced flat chunks, no inter-CTA sync):
//   stream ids chunk -> float out_ids + detect local sub-segment boundaries (smem),
//   then dense float4-sum each sub-segment (2 independent accumulators for MLP)
//   and atomicAdd partials into scratch.
// Kernel 2 (64 CTAs x 256 thr, float4, plain launch — PDL measured a LOSS here:
//   early-resident blocked CTAs steal primary residency): divide sums by counts
//   -> out_avg/out_counts, re-zero scratch (accumulate-from-zero invariant
//   across graph replays).

#define GRID_MAIN (148 * 8)
#define MAX_SEGS 80

__device__ float g_sums[1024 * 64];   // zero at module load; re-zeroed by finalize
__device__ float g_cnt[1024];

__global__ __launch_bounds__(256) void image_sum_kernel(
    const float* __restrict__ x,
    const int* __restrict__ ids,
    float* __restrict__ out_ids,     // [n]
    int n)
{
    const int tid  = threadIdx.x;
    const int cta  = blockIdx.x;
    const int grid = gridDim.x;

    const int n4   = n >> 2;                       // n divisible by 4 here
    const int per  = (n4 + grid - 1) / grid;
    const int b4   = cta * per;
    const int l4   = min(b4 + per, n4);
    if (b4 >= l4) return;

    __shared__ int s_nb;
    __shared__ int s_pos[MAX_SEGS];
    __shared__ int s_img[MAX_SEGS];
    if (tid == 0) s_nb = 0;
    __syncthreads();

    // ---- Phase A: stream ids chunk: convert + record sub-segment starts ----
    {
        const int4*  __restrict__ iv = reinterpret_cast<const int4*>(ids);
        float4* __restrict__ ov = reinterpret_cast<float4*>(out_ids);
        for (int i = b4 + tid; i < l4; i += 256) {
            int4 v = __ldcs(&iv[i]);
            __stcs(&ov[i], make_float4((float)v.x, (float)v.y, (float)v.z, (float)v.w));
            // predecessor id: scalar load (adjacent line, cache-hit); chunk start forced
            int prevw = (i == b4) ? -1 : __ldg(&ids[4 * i - 1]);
            if (v.x != prevw) { int k = atomicAdd(&s_nb, 1); if (k < MAX_SEGS) { s_pos[k] = 4 * i;     s_img[k] = v.x; } }
            if (v.y != v.x)   { int k = atomicAdd(&s_nb, 1); if (k < MAX_SEGS) { s_pos[k] = 4 * i + 1; s_img[k] = v.y; } }
            if (v.z != v.y)   { int k = atomicAdd(&s_nb, 1); if (k < MAX_SEGS) { s_pos[k] = 4 * i + 2; s_img[k] = v.z; } }
            if (v.w != v.z)   { int k = atomicAdd(&s_nb, 1); if (k < MAX_SEGS) { s_pos[k] = 4 * i + 3; s_img[k] = v.w; } }
        }
    }
    __syncthreads();

    // ---- Sort the (few) sub-segment starts by position (thread 0, tiny n) ----
    if (tid == 0) {
        int nb = min(s_nb, MAX_SEGS);
        for (int a = 1; a < nb; a++) {
            int p = s_pos[a], g = s_img[a];
            int bpos = a - 1;
            while (bpos >= 0 && s_pos[bpos] > p) {
                s_pos[bpos + 1] = s_pos[bpos];
                s_img[bpos + 1] = s_img[bpos];
                bpos--;
            }
            s_pos[bpos + 1] = p;
            s_img[bpos + 1] = g;
        }
        s_nb = nb;
    }
    __syncthreads();

    // ---- Phase B: dense sum per sub-segment, atomicAdd partials ----
    const int nb  = s_nb;
    const int col = tid & 15;   // float4 index within the 64-dim row
    const int rl  = tid >> 4;   // row lane 0..15
    const int chunk_end = 4 * l4;
    const float4* __restrict__ xv = reinterpret_cast<const float4*>(x);
    __shared__ float4 sh[256];

    for (int si = 0; si < nb; si++) {
        const int s   = s_pos[si];
        const int e   = (si + 1 < nb) ? s_pos[si + 1] : chunk_end;
        const int img = s_img[si];

        // Two independent accumulators -> 2 outstanding LDG.128 per thread.
        float4 acc0 = make_float4(0.f, 0.f, 0.f, 0.f);
        float4 acc1 = make_float4(0.f, 0.f, 0.f, 0.f);
        int r = s + rl;
        #pragma unroll 2
        for (; r + 16 < e; r += 32) {
            float4 a = __ldcs(&xv[(size_t)r * 16 + col]);
            float4 b = __ldcs(&xv[(size_t)(r + 16) * 16 + col]);
            acc0.x += a.x; acc0.y += a.y; acc0.z += a.z; acc0.w += a.w;
            acc1.x += b.x; acc1.y += b.y; acc1.z += b.z; acc1.w += b.w;
        }
        if (r < e) {
            float4 a = __ldcs(&xv[(size_t)r * 16 + col]);
            acc0.x += a.x; acc0.y += a.y; acc0.z += a.z; acc0.w += a.w;
        }
        acc0.x += acc1.x; acc0.y += acc1.y; acc0.z += acc1.z; acc0.w += acc1.w;

        sh[tid] = acc0;
        __syncthreads();
        #pragma unroll
        for (int st = 128; st >= 16; st >>= 1) {
            if (tid < st) {
                float4 a = sh[tid], b = sh[tid + st];
                a.x += b.x; a.y += b.y; a.z += b.z; a.w += b.w;
                sh[tid] = a;
            }
            __syncthreads();
        }

        if (tid < 16) {
            float4 v = sh[tid];
            float* dst = &g_sums[img * 64 + tid * 4];
            atomicAdd(dst + 0, v.x);
            atomicAdd(dst + 1, v.y);
            atomicAdd(dst + 2, v.z);
            atomicAdd(dst + 3, v.w);
        }
        if (tid == 0) atomicAdd(&g_cnt[img], (float)(e - s));
        __syncthreads();
    }
}

// 64 CTAs x 256 threads, float4-wide: each block finalizes 16 images.
__global__ __launch_bounds__(256) void finalize_kernel(
    float* __restrict__ out_avg,
    float* __restrict__ out_counts,
    int n_images)
{
    const int t = blockIdx.x * 256 + threadIdx.x;   // global float4 slot
    const int nvec = n_images * 16;                 // 64 dims = 16 float4 per image
    if (t >= nvec) return;
    const int img = t >> 4;

    const float c = g_cnt[img];
    const float inv = 1.0f / fmaxf(c, 1.0f);

    float4* __restrict__ sv = reinterpret_cast<float4*>(g_sums);
    float4 v = sv[t];
    v.x *= inv; v.y *= inv; v.z *= inv; v.w *= inv;
    reinterpret_cast<float4*>(out_avg)[t] = v;
    sv[t] = make_float4(0.f, 0.f, 0.f, 0.f);        // reset for next replay

    if ((t & 15) == 0) {
        out_counts[img] = c;
        g_cnt[img] = 0.f;   // lanes of this image are within one warp; reads done
    }
}

extern "C" void kernel_launch(void* const* d_in, const int* in_sizes, int n_in,
                              void* d_out, int out_size) {
    const float* x   = (const float*)d_in[0];
    const int*   ids = (const int*)d_in[1];

    const int n = in_sizes[1];                 // number of rows / reflections
    // out_size = n_images*64 (avg) + n (ids) + n_images (counts)
    const int n_images = (out_size - n) / 65;

    float* out_avg    = (float*)d_out;
    float* out_ids    = out_avg + (size_t)n_images * 64;
    float* out_counts = out_ids + (size_t)n;

    image_sum_kernel<<<GRID_MAIN, 256>>>(x, ids, out_ids, n);
    const int nvec = n_images * 16;
    finalize_kernel<<<(nvec + 255) / 256, 256>>>(out_avg, out_counts, n_images);
}

// round 13
// speedup vs baseline: 1.0948x; 1.0948x over previous
#include <cuda_runtime.h>
#include <cuda_bf16.h>

// ImageAverage: x [N, 64] f32, image_id [N] i32 SORTED ascending in [0, n_images).
// Output (f32 concat): averaged [n_images, 64], image_id as float [N], counts [n_images].
//
// Kernel 1 (grid = 148*8*8 = 9472, 8x oversubscribed flat chunks -> work-stealing
//   smooths the per-SM rate spread tail; logic identical to the proven R8 kernel):
//   stream ids chunk -> float out_ids + detect local sub-segment boundaries (smem),
//   then dense float4-sum each sub-segment (single-acc unroll-4 loop — 2-acc
//   variant measured SLOWER) and atomicAdd partials into scratch.
// Kernel 2 (64 CTAs x 256 thr, float4): divide sums by counts -> out_avg/out_counts,
//   re-zero scratch (accumulate-from-zero invariant across graph replays).

#define GRID_MAIN (148 * 8 * 8)
#define MAX_SEGS 80

__device__ float g_sums[1024 * 64];   // zero at module load; re-zeroed by finalize
__device__ float g_cnt[1024];

__global__ __launch_bounds__(256) void image_sum_kernel(
    const float* __restrict__ x,
    const int* __restrict__ ids,
    float* __restrict__ out_ids,     // [n]
    int n)
{
    const int tid  = threadIdx.x;
    const int cta  = blockIdx.x;
    const int grid = gridDim.x;

    const int n4   = n >> 2;                       // n divisible by 4 here
    const int per  = (n4 + grid - 1) / grid;
    const int b4   = cta * per;
    const int l4   = min(b4 + per, n4);
    if (b4 >= l4) return;

    __shared__ int s_nb;
    __shared__ int s_pos[MAX_SEGS];
    __shared__ int s_img[MAX_SEGS];
    if (tid == 0) s_nb = 0;
    __syncthreads();

    // ---- Phase A: stream ids chunk: convert + record sub-segment starts ----
    {
        const int4*  __restrict__ iv = reinterpret_cast<const int4*>(ids);
        float4* __restrict__ ov = reinterpret_cast<float4*>(out_ids);
        for (int i = b4 + tid; i < l4; i += 256) {
            int4 v = __ldcs(&iv[i]);
            __stcs(&ov[i], make_float4((float)v.x, (float)v.y, (float)v.z, (float)v.w));
            // predecessor id: scalar load (adjacent line, cache-hit); chunk start forced
            int prevw = (i == b4) ? -1 : __ldg(&ids[4 * i - 1]);
            if (v.x != prevw) { int k = atomicAdd(&s_nb, 1); if (k < MAX_SEGS) { s_pos[k] = 4 * i;     s_img[k] = v.x; } }
            if (v.y != v.x)   { int k = atomicAdd(&s_nb, 1); if (k < MAX_SEGS) { s_pos[k] = 4 * i + 1; s_img[k] = v.y; } }
            if (v.z != v.y)   { int k = atomicAdd(&s_nb, 1); if (k < MAX_SEGS) { s_pos[k] = 4 * i + 2; s_img[k] = v.z; } }
            if (v.w != v.z)   { int k = atomicAdd(&s_nb, 1); if (k < MAX_SEGS) { s_pos[k] = 4 * i + 3; s_img[k] = v.w; } }
        }
    }
    __syncthreads();

    // ---- Sort the (few) sub-segment starts by position (thread 0, tiny n) ----
    if (tid == 0) {
        int nb = min(s_nb, MAX_SEGS);
        for (int a = 1; a < nb; a++) {
            int p = s_pos[a], g = s_img[a];
            int bpos = a - 1;
            while (bpos >= 0 && s_pos[bpos] > p) {
                s_pos[bpos + 1] = s_pos[bpos];
                s_img[bpos + 1] = s_img[bpos];
                bpos--;
            }
            s_pos[bpos + 1] = p;
            s_img[bpos + 1] = g;
        }
        s_nb = nb;
    }
    __syncthreads();

    // ---- Phase B: dense sum per sub-segment, atomicAdd partials ----
    const int nb  = s_nb;
    const int col = tid & 15;   // float4 index within the 64-dim row
    const int rl  = tid >> 4;   // row lane 0..15
    const int chunk_end = 4 * l4;
    const float4* __restrict__ xv = reinterpret_cast<const float4*>(x);
    __shared__ float4 sh[256];

    for (int si = 0; si < nb; si++) {
        const int s   = s_pos[si];
        const int e   = (si + 1 < nb) ? s_pos[si + 1] : chunk_end;
        const int img = s_img[si];

        float4 acc = make_float4(0.f, 0.f, 0.f, 0.f);
        #pragma unroll 4
        for (int r = s + rl; r < e; r += 16) {
            float4 v = __ldcs(&xv[(size_t)r * 16 + col]);
            acc.x += v.x; acc.y += v.y; acc.z += v.z; acc.w += v.w;
        }

        sh[tid] = acc;
        __syncthreads();
        #pragma unroll
        for (int st = 128; st >= 16; st >>= 1) {
            if (tid < st) {
                float4 a = sh[tid], b = sh[tid + st];
                a.x += b.x; a.y += b.y; a.z += b.z; a.w += b.w;
                sh[tid] = a;
            }
            __syncthreads();
        }

        if (tid < 16) {
            float4 v = sh[tid];
            float* dst = &g_sums[img * 64 + tid * 4];
            atomicAdd(dst + 0, v.x);
            atomicAdd(dst + 1, v.y);
            atomicAdd(dst + 2, v.z);
            atomicAdd(dst + 3, v.w);
        }
        if (tid == 0) atomicAdd(&g_cnt[img], (float)(e - s));
        __syncthreads();
    }
}

// 64 CTAs x 256 threads, float4-wide: each block finalizes 16 images.
__global__ __launch_bounds__(256) void finalize_kernel(
    float* __restrict__ out_avg,
    float* __restrict__ out_counts,
    int n_images)
{
    const int t = blockIdx.x * 256 + threadIdx.x;   // global float4 slot
    const int nvec = n_images * 16;                 // 64 dims = 16 float4 per image
    if (t >= nvec) return;
    const int img = t >> 4;

    const float c = g_cnt[img];
    const float inv = 1.0f / fmaxf(c, 1.0f);

    float4* __restrict__ sv = reinterpret_cast<float4*>(g_sums);
    float4 v = sv[t];
    v.x *= inv; v.y *= inv; v.z *= inv; v.w *= inv;
    reinterpret_cast<float4*>(out_avg)[t] = v;
    sv[t] = make_float4(0.f, 0.f, 0.f, 0.f);        // reset for next replay

    if ((t & 15) == 0) {
        out_counts[img] = c;
        g_cnt[img] = 0.f;   // lanes of this image are within one warp; reads done
    }
}

extern "C" void kernel_launch(void* const* d_in, const int* in_sizes, int n_in,
                              void* d_out, int out_size) {
    const float* x   = (const float*)d_in[0];
    const int*   ids = (const int*)d_in[1];

    const int n = in_sizes[1];                 // number of rows / reflections
    // out_size = n_images*64 (avg) + n (ids) + n_images (counts)
    const int n_images = (out_size - n) / 65;

    float* out_avg    = (float*)d_out;
    float* out_ids    = out_avg + (size_t)n_images * 64;
    float* out_counts = out_ids + (size_t)n;

    image_sum_kernel<<<GRID_MAIN, 256>>>(x, ids, out_ids, n);
    const int nvec = n_images * 16;
    finalize_kernel<<<(nvec + 255) / 256, 256>>>(out_avg, out_counts, n_images);
}